// round 6
// baseline (speedup 1.0000x reference)
#include <cuda_runtime.h>
#include <cuda_bf16.h>
#include <cstdint>

#define D 512
#define NDRUGS 4096
#define BM 128
#define BN 128
#define BK 64

// ---------------- device scratch (allocation-free) ----------------
__device__ __align__(1024) __nv_bfloat16  g_Uh[NDRUGS * D];    // 4 MB (U = (z*d)@W, bf16)
__device__ __align__(1024) __nv_bfloat16  g_Ah[NDRUGS * D];    // 4 MB (hi of z*d)
__device__ __align__(16)   __nv_bfloat16  g_Al[NDRUGS * D];    // 4 MB (lo of z*d)
__device__ __align__(16)   __nv_bfloat16  g_Bh[D * D];         // 512 KB (W^T hi)
__device__ __align__(16)   __nv_bfloat16  g_Bl[D * D];         // 512 KB (W^T lo)

// ---------------- helpers ----------------
__device__ __forceinline__ uint32_t smem_to_u32(const void* p) {
    uint32_t a;
    asm("{ .reg .u64 t; cvta.to.shared.u64 t, %1; cvt.u32.u64 %0, t; }" : "=r"(a) : "l"(p));
    return a;
}
#define SMEM_SWIZZLE_128B(o) ((o) ^ (((o) >> 3) & 0x70))

#define CP_ASYNC16(dst, src) \
    asm volatile("cp.async.cg.shared.global [%0], [%1], 16;" :: "r"(dst), "l"(src))
#define CP_ASYNC16_CA(dst, src) \
    asm volatile("cp.async.ca.shared.global [%0], [%1], 16;" :: "r"(dst), "l"(src))
#define CP_COMMIT() asm volatile("cp.async.commit_group;" ::: "memory")
#define CP_WAIT(n)  asm volatile("cp.async.wait_group %0;" :: "n"(n) : "memory")

__device__ __forceinline__ void ldsm_x4(uint32_t& r0, uint32_t& r1, uint32_t& r2, uint32_t& r3,
                                        uint32_t addr) {
    asm volatile("ldmatrix.sync.aligned.m8n8.x4.shared.b16 {%0,%1,%2,%3}, [%4];"
                 : "=r"(r0), "=r"(r1), "=r"(r2), "=r"(r3) : "r"(addr));
}
__device__ __forceinline__ void mma_bf16(float* c, const uint32_t* a, uint32_t b0, uint32_t b1) {
    asm volatile("mma.sync.aligned.m16n8k16.row.col.f32.bf16.bf16.f32 "
                 "{%0,%1,%2,%3}, {%4,%5,%6,%7}, {%8,%9}, {%0,%1,%2,%3};"
                 : "+f"(c[0]), "+f"(c[1]), "+f"(c[2]), "+f"(c[3])
                 : "r"(a[0]), "r"(a[1]), "r"(a[2]), "r"(a[3]), "r"(b0), "r"(b1));
}

// GEMM SMEM: 2 stages x (Ah 16K | Al 16K | Bh 16K | Bl 16K)
#define STAGE_BYTES 65536
#define AH_OFF 0
#define AL_OFF 16384
#define BH_OFF 32768
#define BL_OFF 49152
#define SM_GEMM (2 * STAGE_BYTES)

// ---------------------------------------------------------------------------
// Prep A: Ah/Al = split-bf16 of z[m,k] * d[k]
// ---------------------------------------------------------------------------
__global__ __launch_bounds__(256) void prep_a_kernel(
    const float* __restrict__ z, const float* __restrict__ ldiag, const int* __restrict__ idxp)
{
    const float* dp = ldiag + idxp[0] * D;
    int i = blockIdx.x * 256 + threadIdx.x;     // float4 index over NDRUGS*D/4
    int k4 = (i & (D / 4 - 1)) << 2;
    float4 v = ((const float4*)z)[i];
    v.x *= dp[k4 + 0]; v.y *= dp[k4 + 1]; v.z *= dp[k4 + 2]; v.w *= dp[k4 + 3];

    __nv_bfloat16 hx = __float2bfloat16(v.x), hy = __float2bfloat16(v.y);
    __nv_bfloat16 hz = __float2bfloat16(v.z), hw = __float2bfloat16(v.w);
    __nv_bfloat16 lx = __float2bfloat16(v.x - __bfloat162float(hx));
    __nv_bfloat16 ly = __float2bfloat16(v.y - __bfloat162float(hy));
    __nv_bfloat16 lz = __float2bfloat16(v.z - __bfloat162float(hz));
    __nv_bfloat16 lw = __float2bfloat16(v.w - __bfloat162float(hw));

    __nv_bfloat162 h01{hx, hy}, h23{hz, hw}, l01{lx, ly}, l23{lz, lw};
    uint2 hp, lp;
    hp.x = *(uint32_t*)&h01; hp.y = *(uint32_t*)&h23;
    lp.x = *(uint32_t*)&l01; lp.y = *(uint32_t*)&l23;
    ((uint2*)g_Ah)[i] = hp;
    ((uint2*)g_Al)[i] = lp;
}

// ---------------------------------------------------------------------------
// Prep W: Bt[n,k] = W[k,n], split-bf16
// ---------------------------------------------------------------------------
__global__ __launch_bounds__(256) void prep_w_kernel(const float* __restrict__ W)
{
    __shared__ float t[32][33];
    int tx = threadIdx.x, ty = threadIdx.y;
    int x0 = blockIdx.x * 32, y0 = blockIdx.y * 32;
    #pragma unroll
    for (int r = 0; r < 4; r++)
        t[ty + r * 8][tx] = W[(y0 + ty + r * 8) * D + x0 + tx];
    __syncthreads();
    #pragma unroll
    for (int r = 0; r < 4; r++) {
        int n = x0 + ty + r * 8;
        int k = y0 + tx;
        float v = t[tx][ty + r * 8];
        __nv_bfloat16 h = __float2bfloat16(v);
        __nv_bfloat16 l = __float2bfloat16(v - __bfloat162float(h));
        g_Bh[n * D + k] = h;
        g_Bl[n * D + k] = l;
    }
}

// ---------------------------------------------------------------------------
// Split-bf16 GEMM via mma.sync (HMMA): Uh = bf16( (Z*d) @ W )
// grid (D/BN=4, NDRUGS/BM=32), 256 threads, double-buffered cp.async
// ---------------------------------------------------------------------------
__global__ __launch_bounds__(256, 1) void dedicom_mma_kernel()
{
    extern __shared__ char smem[];
    const int tid  = threadIdx.x;
    const int wid  = tid >> 5;
    const int lane = tid & 31;
    const int m0 = blockIdx.y * BM;
    const int n0 = blockIdx.x * BN;
    const uint32_t sbase = smem_to_u32(smem);

    const int wm = (wid & 3) * 32;
    const int wn = (wid >> 2) * 64;

    float acc[2][8][4];
    #pragma unroll
    for (int a = 0; a < 2; a++)
        #pragma unroll
        for (int b = 0; b < 8; b++)
            #pragma unroll
            for (int c = 0; c < 4; c++) acc[a][b][c] = 0.f;

    auto load_stage = [&](int kc, int stg) {
        const int k0 = kc * BK;
        const uint32_t b = sbase + stg * STAGE_BYTES;
        #pragma unroll
        for (int t = tid; t < 1024; t += 256) {
            int m = t >> 3, j = t & 7;
            uint32_t sw = SMEM_SWIZZLE_128B((uint32_t)(m * 128 + j * 16));
            CP_ASYNC16(b + AH_OFF + sw, (const char*)(g_Ah + (m0 + m) * D + k0) + j * 16);
            CP_ASYNC16(b + AL_OFF + sw, (const char*)(g_Al + (m0 + m) * D + k0) + j * 16);
            CP_ASYNC16(b + BH_OFF + sw, (const char*)(g_Bh + (n0 + m) * D + k0) + j * 16);
            CP_ASYNC16(b + BL_OFF + sw, (const char*)(g_Bl + (n0 + m) * D + k0) + j * 16);
        }
    };

    load_stage(0, 0); CP_COMMIT();

    const int NKC = D / BK;   // 8
    for (int kc = 0; kc < NKC; kc++) {
        if (kc + 1 < NKC) { load_stage(kc + 1, (kc + 1) & 1); CP_COMMIT(); CP_WAIT(1); }
        else              { CP_WAIT(0); }
        __syncthreads();

        const uint32_t sb = sbase + (kc & 1) * STAGE_BYTES;

        #pragma unroll
        for (int ks = 0; ks < BK / 16; ks++) {
            uint32_t ah[2][4], al[2][4], bh[4][4], bl[4][4];

            #pragma unroll
            for (int mt = 0; mt < 2; mt++) {
                uint32_t off = SMEM_SWIZZLE_128B(
                    (uint32_t)((wm + mt * 16 + (lane & 15)) * 128 + ks * 32 + (lane >> 4) * 16));
                ldsm_x4(ah[mt][0], ah[mt][1], ah[mt][2], ah[mt][3], sb + AH_OFF + off);
                ldsm_x4(al[mt][0], al[mt][1], al[mt][2], al[mt][3], sb + AL_OFF + off);
            }
            #pragma unroll
            for (int p = 0; p < 4; p++) {
                uint32_t off = SMEM_SWIZZLE_128B(
                    (uint32_t)((wn + p * 16 + ((lane >> 4) * 8) + (lane & 7)) * 128
                               + ks * 32 + ((lane >> 3) & 1) * 16));
                ldsm_x4(bh[p][0], bh[p][1], bh[p][2], bh[p][3], sb + BH_OFF + off);
                ldsm_x4(bl[p][0], bl[p][1], bl[p][2], bl[p][3], sb + BL_OFF + off);
            }
            #pragma unroll
            for (int mt = 0; mt < 2; mt++) {
                #pragma unroll
                for (int p = 0; p < 4; p++) {
                    mma_bf16(acc[mt][2 * p + 0], ah[mt], bh[p][0], bh[p][1]);
                    mma_bf16(acc[mt][2 * p + 0], ah[mt], bl[p][0], bl[p][1]);
                    mma_bf16(acc[mt][2 * p + 0], al[mt], bh[p][0], bh[p][1]);
                    mma_bf16(acc[mt][2 * p + 1], ah[mt], bh[p][2], bh[p][3]);
                    mma_bf16(acc[mt][2 * p + 1], ah[mt], bl[p][2], bl[p][3]);
                    mma_bf16(acc[mt][2 * p + 1], al[mt], bh[p][2], bh[p][3]);
                }
            }
        }
        __syncthreads();
    }

    // epilogue: write Uh as bf16 pairs (no diag scale — folded into edge col side)
    const int g  = lane >> 2;
    const int c2 = (lane & 3) * 2;
    #pragma unroll
    for (int mt = 0; mt < 2; mt++) {
        const int row0 = m0 + wm + mt * 16 + g;
        #pragma unroll
        for (int nt = 0; nt < 8; nt++) {
            const int col = wn + nt * 8 + c2;
            __nv_bfloat162 v0 = __floats2bfloat162_rn(acc[mt][nt][0], acc[mt][nt][1]);
            __nv_bfloat162 v1 = __floats2bfloat162_rn(acc[mt][nt][2], acc[mt][nt][3]);
            *(__nv_bfloat162*)(g_Uh + (long)row0 * D + n0 + col)       = v0;
            *(__nv_bfloat162*)(g_Uh + (long)(row0 + 8) * D + n0 + col) = v1;
        }
    }
}

// ---------------------------------------------------------------------------
// Phase 2 (tensor-core): per warp, 16 edges.
//   A (16 x k) = Uh rows of the 16 edges' r-indices
//   B (16 x k) = Ah rows of the 16 edges' c-indices
//   C1 = A x B[0:8]  -> diag C1[t][t]   = score(edge t),   t = 0..7
//   C2 = A x B[8:16] -> C2[8+t][t]      = score(edge 8+t)
// Staged in k-chunks of 64 elems (128B/row), padded stride 144B (conflict-free
// per-lane ldmatrix addresses), double-buffered cp.async.
// ---------------------------------------------------------------------------
#define EG 16
#define KCH 64
#define NCHUNK (D / KCH)              // 8
#define ROW_B 144                     // 128B data + 16B pad
#define SIDE_B (16 * ROW_B)           // 2304
#define WSTAGE (4 * SIDE_B)           // A0,B0,A1,B1 = 9216 per warp
#define IDX_OFF (8 * WSTAGE)          // 73728
#define SM_EDGE (IDX_OFF + 8 * 32 * 4)  // 74752

__global__ __launch_bounds__(256) void dedicom_edge_mma_kernel(
    const int* __restrict__ edges, float* __restrict__ out, int n_edges)
{
    extern __shared__ char smem[];
    const uint32_t sbase = smem_to_u32(smem);
    const int tid = threadIdx.x, wid = tid >> 5, lane = tid & 31;
    const int group = blockIdx.x * 8 + wid;
    const int e0 = group * EG;
    if (e0 >= n_edges) return;

    int* sidx = (int*)(smem + IDX_OFF) + wid * 32;
    {   // lanes 0-15: r indices, lanes 16-31: c indices
        int t = lane & 15;
        int e = e0 + t;
        int idx = 0;
        if (e < n_edges) idx = (lane < 16) ? edges[e] : edges[n_edges + e];
        sidx[lane] = idx * 1024;      // pre-scaled to row byte offset (1KB rows)
    }
    __syncwarp();

    const uint32_t st0 = sbase + wid * WSTAGE;
    const char* baseU = (const char*)g_Uh;
    const char* baseA = (const char*)g_Ah;

    auto stage_chunk = [&](int ck, int buf) {
        const uint32_t sA = st0 + buf * (2 * SIDE_B);
        const uint32_t sB = sA + SIDE_B;
        const int cko = ck * 128;     // byte offset within row
        #pragma unroll
        for (int i = 0; i < 4; i++) {
            int g   = i * 32 + lane;  // 0..127 over 16 rows x 8 chunks16B
            int row = g >> 3;
            int c16 = (g & 7) * 16;
            uint32_t so = (uint32_t)(row * ROW_B + c16);
            CP_ASYNC16_CA(sA + so, baseU + (long)sidx[row]      + cko + c16);
            CP_ASYNC16_CA(sB + so, baseA + (long)sidx[16 + row] + cko + c16);
        }
        CP_COMMIT();
    };

    float c1[4] = {0.f, 0.f, 0.f, 0.f};
    float c2[4] = {0.f, 0.f, 0.f, 0.f};

    stage_chunk(0, 0);
    #pragma unroll
    for (int ck = 0; ck < NCHUNK; ck++) {
        if (ck + 1 < NCHUNK) { stage_chunk(ck + 1, (ck + 1) & 1); CP_WAIT(1); }
        else                 { CP_WAIT(0); }
        __syncwarp();

        const uint32_t sA = st0 + (ck & 1) * (2 * SIDE_B);
        const uint32_t sB = sA + SIDE_B;

        #pragma unroll
        for (int ks = 0; ks < KCH / 16; ks++) {   // 4
            uint32_t a[4], b[4];
            ldsm_x4(a[0], a[1], a[2], a[3],
                    sA + (uint32_t)((lane & 15) * ROW_B + ks * 32 + (lane >> 4) * 16));
            ldsm_x4(b[0], b[1], b[2], b[3],
                    sB + (uint32_t)((((lane >> 4) * 8) + (lane & 7)) * ROW_B
                                    + ks * 32 + ((lane >> 3) & 1) * 16));
            mma_bf16(c1, a, b[0], b[1]);   // cols 0-7  -> edges 0-7 on diag
            mma_bf16(c2, a, b[2], b[3]);   // cols 8-15 -> edges 8-15 at [8+t][t]
        }
    }

    // diagonal extraction: lane owns edge t (via c1) and edge 8+t (via c2)
    // C frag: c0 at (row=lane>>2, col=2*(lane&3)), c1 at col+1;
    //         c2 at (row=(lane>>2)+8, col=2*(lane&3)), c3 at col+1.
    const int t    = lane >> 2;
    const int col0 = 2 * (lane & 3);
    float s1, s2; bool own = false;
    if (col0 == t)          { s1 = c1[0]; s2 = c2[2]; own = true; }
    else if (col0 + 1 == t) { s1 = c1[1]; s2 = c2[3]; own = true; }
    if (own) {
        int ea = e0 + t, eb = e0 + 8 + t;
        if (ea < n_edges) out[ea] = 1.f / (1.f + __expf(-s1));
        if (eb < n_edges) out[eb] = 1.f / (1.f + __expf(-s2));
    }
}

// ---------------------------------------------------------------------------
// Launch
// ---------------------------------------------------------------------------
extern "C" void kernel_launch(void* const* d_in, const int* in_sizes, int n_in,
                              void* d_out, int out_size)
{
    const float* z     = (const float*)d_in[0];   // [4096, 512]
    const float* W     = (const float*)d_in[1];   // [512, 512]
    const float* ldiag = (const float*)d_in[2];   // [10, 512]
    const int*   edges = (const int*)d_in[3];     // [2, n_edges] int32
    const int*   idxp  = (const int*)d_in[4];     // scalar

    const int n_drugs = in_sizes[0] / D;
    const int n_edges = in_sizes[3] / 2;

    static int smem_set = 0;
    if (!smem_set) {
        cudaFuncSetAttribute(dedicom_mma_kernel,
                             cudaFuncAttributeMaxDynamicSharedMemorySize, SM_GEMM);
        cudaFuncSetAttribute(dedicom_edge_mma_kernel,
                             cudaFuncAttributeMaxDynamicSharedMemorySize, SM_EDGE);
        smem_set = 1;
    }

    prep_a_kernel<<<(n_drugs * D / 4 + 255) / 256, 256>>>(z, ldiag, idxp);
    prep_w_kernel<<<dim3(D / 32, D / 32), dim3(32, 8)>>>(W);

    dim3 gm(D / BN, n_drugs / BM);
    dedicom_mma_kernel<<<gm, 256, SM_GEMM>>>();

    int blocks = (n_edges + 8 * EG - 1) / (8 * EG);
    dedicom_edge_mma_kernel<<<blocks, 256, SM_EDGE>>>(edges, (float*)d_out, n_edges);
}

// round 7
// speedup vs baseline: 2.0865x; 2.0865x over previous
#include <cuda_runtime.h>
#include <cuda_bf16.h>
#include <cstdint>

#define D 512
#define NDRUGS 4096
#define BM 128
#define BN 128
#define BK 64

// ---------------- device scratch (allocation-free) ----------------
__device__ __align__(16) __nv_bfloat16  g_Uh[NDRUGS * D];    // 4 MB (U = (z*d)@W, bf16)
__device__ __align__(16) __nv_bfloat16  g_Ah[NDRUGS * D];    // 4 MB (bf16 of z*d)
__device__ __align__(16) __nv_bfloat16  g_Bh[D * D];         // 512 KB (W^T hi)
__device__ __align__(16) __nv_bfloat16  g_Bl[D * D];         // 512 KB (W^T lo)

// ---------------- helpers ----------------
__device__ __forceinline__ uint32_t smem_to_u32(const void* p) {
    uint32_t a;
    asm("{ .reg .u64 t; cvta.to.shared.u64 t, %1; cvt.u32.u64 %0, t; }" : "=r"(a) : "l"(p));
    return a;
}
#define SMEM_SWIZZLE_128B(o) ((o) ^ (((o) >> 3) & 0x70))

#define CP_ASYNC16(dst, src) \
    asm volatile("cp.async.cg.shared.global [%0], [%1], 16;" :: "r"(dst), "l"(src))
#define CP_COMMIT() asm volatile("cp.async.commit_group;" ::: "memory")
#define CP_WAIT(n)  asm volatile("cp.async.wait_group %0;" :: "n"(n) : "memory")

__device__ __forceinline__ void ldsm_x4(uint32_t& r0, uint32_t& r1, uint32_t& r2, uint32_t& r3,
                                        uint32_t addr) {
    asm volatile("ldmatrix.sync.aligned.m8n8.x4.shared.b16 {%0,%1,%2,%3}, [%4];"
                 : "=r"(r0), "=r"(r1), "=r"(r2), "=r"(r3) : "r"(addr));
}
__device__ __forceinline__ void mma_bf16(float* c, const uint32_t* a, uint32_t b0, uint32_t b1) {
    asm volatile("mma.sync.aligned.m16n8k16.row.col.f32.bf16.bf16.f32 "
                 "{%0,%1,%2,%3}, {%4,%5,%6,%7}, {%8,%9}, {%0,%1,%2,%3};"
                 : "+f"(c[0]), "+f"(c[1]), "+f"(c[2]), "+f"(c[3])
                 : "r"(a[0]), "r"(a[1]), "r"(a[2]), "r"(a[3]), "r"(b0), "r"(b1));
}

// GEMM SMEM: 2 stages x (Ah 16K | Bh 16K | Bl 16K) = 96 KB
#define STAGE_BYTES 49152
#define AH_OFF 0
#define BH_OFF 16384
#define BL_OFF 32768
#define SM_GEMM (2 * STAGE_BYTES)

// ---------------------------------------------------------------------------
// Prep A: Ah = bf16(z[m,k] * d[k])
// ---------------------------------------------------------------------------
__global__ __launch_bounds__(256) void prep_a_kernel(
    const float* __restrict__ z, const float* __restrict__ ldiag, const int* __restrict__ idxp)
{
    const float* dp = ldiag + idxp[0] * D;
    int i = blockIdx.x * 256 + threadIdx.x;     // float4 index over NDRUGS*D/4
    int k4 = (i & (D / 4 - 1)) << 2;
    float4 v = ((const float4*)z)[i];
    v.x *= dp[k4 + 0]; v.y *= dp[k4 + 1]; v.z *= dp[k4 + 2]; v.w *= dp[k4 + 3];

    __nv_bfloat162 h01 = __floats2bfloat162_rn(v.x, v.y);
    __nv_bfloat162 h23 = __floats2bfloat162_rn(v.z, v.w);
    uint2 hp; hp.x = *(uint32_t*)&h01; hp.y = *(uint32_t*)&h23;
    ((uint2*)g_Ah)[i] = hp;
}

// ---------------------------------------------------------------------------
// Prep W: Bt[n,k] = W[k,n], split-bf16 (hi + residual)
// ---------------------------------------------------------------------------
__global__ __launch_bounds__(256) void prep_w_kernel(const float* __restrict__ W)
{
    __shared__ float t[32][33];
    int tx = threadIdx.x, ty = threadIdx.y;
    int x0 = blockIdx.x * 32, y0 = blockIdx.y * 32;
    #pragma unroll
    for (int r = 0; r < 4; r++)
        t[ty + r * 8][tx] = W[(y0 + ty + r * 8) * D + x0 + tx];
    __syncthreads();
    #pragma unroll
    for (int r = 0; r < 4; r++) {
        int n = x0 + ty + r * 8;
        int k = y0 + tx;
        float v = t[tx][ty + r * 8];
        __nv_bfloat16 h = __float2bfloat16(v);
        __nv_bfloat16 l = __float2bfloat16(v - __bfloat162float(h));
        g_Bh[n * D + k] = h;
        g_Bl[n * D + k] = l;
    }
}

// ---------------------------------------------------------------------------
// 2-product split-W GEMM via mma.sync: Uh = bf16( Ah @ (Wh + Wl) )
// grid (D/BN=4, NDRUGS/BM=32), 256 threads, double-buffered cp.async
// ---------------------------------------------------------------------------
__global__ __launch_bounds__(256, 1) void dedicom_mma_kernel()
{
    extern __shared__ char smem[];
    const int tid  = threadIdx.x;
    const int wid  = tid >> 5;
    const int lane = tid & 31;
    const int m0 = blockIdx.y * BM;
    const int n0 = blockIdx.x * BN;
    const uint32_t sbase = smem_to_u32(smem);

    const int wm = (wid & 3) * 32;
    const int wn = (wid >> 2) * 64;

    float acc[2][8][4];
    #pragma unroll
    for (int a = 0; a < 2; a++)
        #pragma unroll
        for (int b = 0; b < 8; b++)
            #pragma unroll
            for (int c = 0; c < 4; c++) acc[a][b][c] = 0.f;

    auto load_stage = [&](int kc, int stg) {
        const int k0 = kc * BK;
        const uint32_t b = sbase + stg * STAGE_BYTES;
        #pragma unroll
        for (int t = tid; t < 1024; t += 256) {
            int m = t >> 3, j = t & 7;
            uint32_t sw = SMEM_SWIZZLE_128B((uint32_t)(m * 128 + j * 16));
            CP_ASYNC16(b + AH_OFF + sw, (const char*)(g_Ah + (m0 + m) * D + k0) + j * 16);
            CP_ASYNC16(b + BH_OFF + sw, (const char*)(g_Bh + (n0 + m) * D + k0) + j * 16);
            CP_ASYNC16(b + BL_OFF + sw, (const char*)(g_Bl + (n0 + m) * D + k0) + j * 16);
        }
    };

    load_stage(0, 0); CP_COMMIT();

    const int NKC = D / BK;   // 8
    for (int kc = 0; kc < NKC; kc++) {
        if (kc + 1 < NKC) { load_stage(kc + 1, (kc + 1) & 1); CP_COMMIT(); CP_WAIT(1); }
        else              { CP_WAIT(0); }
        __syncthreads();

        const uint32_t sb = sbase + (kc & 1) * STAGE_BYTES;

        #pragma unroll
        for (int ks = 0; ks < BK / 16; ks++) {
            uint32_t ah[2][4], bh[4][4], bl[4][4];

            #pragma unroll
            for (int mt = 0; mt < 2; mt++) {
                uint32_t off = SMEM_SWIZZLE_128B(
                    (uint32_t)((wm + mt * 16 + (lane & 15)) * 128 + ks * 32 + (lane >> 4) * 16));
                ldsm_x4(ah[mt][0], ah[mt][1], ah[mt][2], ah[mt][3], sb + AH_OFF + off);
            }
            #pragma unroll
            for (int p = 0; p < 4; p++) {
                uint32_t off = SMEM_SWIZZLE_128B(
                    (uint32_t)((wn + p * 16 + ((lane >> 4) * 8) + (lane & 7)) * 128
                               + ks * 32 + ((lane >> 3) & 1) * 16));
                ldsm_x4(bh[p][0], bh[p][1], bh[p][2], bh[p][3], sb + BH_OFF + off);
                ldsm_x4(bl[p][0], bl[p][1], bl[p][2], bl[p][3], sb + BL_OFF + off);
            }
            #pragma unroll
            for (int mt = 0; mt < 2; mt++) {
                #pragma unroll
                for (int p = 0; p < 4; p++) {
                    mma_bf16(acc[mt][2 * p + 0], ah[mt], bh[p][0], bh[p][1]);
                    mma_bf16(acc[mt][2 * p + 0], ah[mt], bl[p][0], bl[p][1]);
                    mma_bf16(acc[mt][2 * p + 1], ah[mt], bh[p][2], bh[p][3]);
                    mma_bf16(acc[mt][2 * p + 1], ah[mt], bl[p][2], bl[p][3]);
                }
            }
        }
        __syncthreads();
    }

    // epilogue: write Uh as bf16 pairs (no diag scale — folded into edge col side)
    const int g  = lane >> 2;
    const int c2 = (lane & 3) * 2;
    #pragma unroll
    for (int mt = 0; mt < 2; mt++) {
        const int row0 = m0 + wm + mt * 16 + g;
        #pragma unroll
        for (int nt = 0; nt < 8; nt++) {
            const int col = wn + nt * 8 + c2;
            __nv_bfloat162 v0 = __floats2bfloat162_rn(acc[mt][nt][0], acc[mt][nt][1]);
            __nv_bfloat162 v1 = __floats2bfloat162_rn(acc[mt][nt][2], acc[mt][nt][3]);
            *(__nv_bfloat162*)(g_Uh + (long)row0 * D + n0 + col)       = v0;
            *(__nv_bfloat162*)(g_Uh + (long)(row0 + 8) * D + n0 + col) = v1;
        }
    }
}

// ---------------------------------------------------------------------------
// Phase 2: one warp per edge — score = Uh[r] . Ah[c], bf16 ops, fp32 accum.
// 4 independent accumulators to break the FMA dependency chain.
// ---------------------------------------------------------------------------
__global__ __launch_bounds__(256) void dedicom_edge_kernel(
    const int* __restrict__ edges,
    float* __restrict__ out,
    int n_edges)
{
    const int w    = (blockIdx.x * blockDim.x + threadIdx.x) >> 5;
    const int lane = threadIdx.x & 31;
    if (w >= n_edges) return;

    const int r = edges[w];
    const int c = edges[n_edges + w];

    const uint4* vr = (const uint4*)(g_Uh + (long)r * D);   // 64 uint4 per row
    const uint4* zc = (const uint4*)(g_Ah + (long)c * D);

    float a0 = 0.f, a1 = 0.f, a2 = 0.f, a3 = 0.f;
    #pragma unroll
    for (int i = 0; i < 2; i++) {
        uint4 a = __ldg(&vr[lane + i * 32]);
        uint4 b = __ldg(&zc[lane + i * 32]);
        float2 fa, fb;
        fa = __bfloat1622float2(*(const __nv_bfloat162*)&a.x);
        fb = __bfloat1622float2(*(const __nv_bfloat162*)&b.x);
        a0 = fmaf(fa.x, fb.x, a0); a0 = fmaf(fa.y, fb.y, a0);
        fa = __bfloat1622float2(*(const __nv_bfloat162*)&a.y);
        fb = __bfloat1622float2(*(const __nv_bfloat162*)&b.y);
        a1 = fmaf(fa.x, fb.x, a1); a1 = fmaf(fa.y, fb.y, a1);
        fa = __bfloat1622float2(*(const __nv_bfloat162*)&a.z);
        fb = __bfloat1622float2(*(const __nv_bfloat162*)&b.z);
        a2 = fmaf(fa.x, fb.x, a2); a2 = fmaf(fa.y, fb.y, a2);
        fa = __bfloat1622float2(*(const __nv_bfloat162*)&a.w);
        fb = __bfloat1622float2(*(const __nv_bfloat162*)&b.w);
        a3 = fmaf(fa.x, fb.x, a3); a3 = fmaf(fa.y, fb.y, a3);
    }
    float acc = (a0 + a1) + (a2 + a3);
    #pragma unroll
    for (int o = 16; o; o >>= 1) acc += __shfl_xor_sync(0xffffffffu, acc, o);

    if (lane == 0) out[w] = 1.f / (1.f + __expf(-acc));
}

// ---------------------------------------------------------------------------
// Launch
// ---------------------------------------------------------------------------
extern "C" void kernel_launch(void* const* d_in, const int* in_sizes, int n_in,
                              void* d_out, int out_size)
{
    const float* z     = (const float*)d_in[0];   // [4096, 512]
    const float* W     = (const float*)d_in[1];   // [512, 512]
    const float* ldiag = (const float*)d_in[2];   // [10, 512]
    const int*   edges = (const int*)d_in[3];     // [2, n_edges] int32
    const int*   idxp  = (const int*)d_in[4];     // scalar

    const int n_drugs = in_sizes[0] / D;
    const int n_edges = in_sizes[3] / 2;

    static int smem_set = 0;
    if (!smem_set) {
        cudaFuncSetAttribute(dedicom_mma_kernel,
                             cudaFuncAttributeMaxDynamicSharedMemorySize, SM_GEMM);
        smem_set = 1;
    }

    prep_a_kernel<<<(n_drugs * D / 4 + 255) / 256, 256>>>(z, ldiag, idxp);
    prep_w_kernel<<<dim3(D / 32, D / 32), dim3(32, 8)>>>(W);

    dim3 gm(D / BN, n_drugs / BM);
    dedicom_mma_kernel<<<gm, 256, SM_GEMM>>>();

    int blocks = (n_edges + 7) / 8;
    dedicom_edge_kernel<<<blocks, 256>>>(edges, (float*)d_out, n_edges);
}

// round 8
// speedup vs baseline: 2.1950x; 1.0520x over previous
#include <cuda_runtime.h>
#include <cuda_bf16.h>
#include <cstdint>

#define D 512
#define NDRUGS 4096
#define BM 128
#define BN 128
#define BK 64

// ---------------- device scratch (allocation-free) ----------------
__device__ __align__(16) __nv_bfloat16  g_Uh[NDRUGS * D];    // 4 MB (U = (z*d)@W, bf16)
__device__ __align__(16) __nv_bfloat16  g_Ah[NDRUGS * D];    // 4 MB (bf16 of z*d)
__device__ __align__(16) __nv_bfloat16  g_Bh[D * D];         // 512 KB (W^T hi)
__device__ __align__(16) __nv_bfloat16  g_Bl[D * D];         // 512 KB (W^T lo)

// ---------------- helpers ----------------
__device__ __forceinline__ uint32_t smem_to_u32(const void* p) {
    uint32_t a;
    asm("{ .reg .u64 t; cvta.to.shared.u64 t, %1; cvt.u32.u64 %0, t; }" : "=r"(a) : "l"(p));
    return a;
}
#define SMEM_SWIZZLE_128B(o) ((o) ^ (((o) >> 3) & 0x70))

#define CP_ASYNC16(dst, src) \
    asm volatile("cp.async.cg.shared.global [%0], [%1], 16;" :: "r"(dst), "l"(src))
#define CP_COMMIT() asm volatile("cp.async.commit_group;" ::: "memory")
#define CP_WAIT(n)  asm volatile("cp.async.wait_group %0;" :: "n"(n) : "memory")

__device__ __forceinline__ void ldsm_x4(uint32_t& r0, uint32_t& r1, uint32_t& r2, uint32_t& r3,
                                        uint32_t addr) {
    asm volatile("ldmatrix.sync.aligned.m8n8.x4.shared.b16 {%0,%1,%2,%3}, [%4];"
                 : "=r"(r0), "=r"(r1), "=r"(r2), "=r"(r3) : "r"(addr));
}
__device__ __forceinline__ void mma_bf16(float* c, const uint32_t* a, uint32_t b0, uint32_t b1) {
    asm volatile("mma.sync.aligned.m16n8k16.row.col.f32.bf16.bf16.f32 "
                 "{%0,%1,%2,%3}, {%4,%5,%6,%7}, {%8,%9}, {%0,%1,%2,%3};"
                 : "+f"(c[0]), "+f"(c[1]), "+f"(c[2]), "+f"(c[3])
                 : "r"(a[0]), "r"(a[1]), "r"(a[2]), "r"(a[3]), "r"(b0), "r"(b1));
}

// GEMM SMEM: 2 stages x (Ah 16K | Bh 16K | Bl 16K) = 96 KB
#define STAGE_BYTES 49152
#define AH_OFF 0
#define BH_OFF 16384
#define BL_OFF 32768
#define SM_GEMM (2 * STAGE_BYTES)

// ---------------------------------------------------------------------------
// Prep A: Ah = bf16(z[m,k] * d[k])
// ---------------------------------------------------------------------------
__global__ __launch_bounds__(256) void prep_a_kernel(
    const float* __restrict__ z, const float* __restrict__ ldiag, const int* __restrict__ idxp)
{
    const float* dp = ldiag + idxp[0] * D;
    int i = blockIdx.x * 256 + threadIdx.x;     // float4 index over NDRUGS*D/4
    int k4 = (i & (D / 4 - 1)) << 2;
    float4 v = ((const float4*)z)[i];
    v.x *= dp[k4 + 0]; v.y *= dp[k4 + 1]; v.z *= dp[k4 + 2]; v.w *= dp[k4 + 3];

    __nv_bfloat162 h01 = __floats2bfloat162_rn(v.x, v.y);
    __nv_bfloat162 h23 = __floats2bfloat162_rn(v.z, v.w);
    uint2 hp; hp.x = *(uint32_t*)&h01; hp.y = *(uint32_t*)&h23;
    ((uint2*)g_Ah)[i] = hp;
}

// ---------------------------------------------------------------------------
// Prep W: Bt[n,k] = W[k,n], split-bf16 (hi + residual)
// ---------------------------------------------------------------------------
__global__ __launch_bounds__(256) void prep_w_kernel(const float* __restrict__ W)
{
    __shared__ float t[32][33];
    int tx = threadIdx.x, ty = threadIdx.y;
    int x0 = blockIdx.x * 32, y0 = blockIdx.y * 32;
    #pragma unroll
    for (int r = 0; r < 4; r++)
        t[ty + r * 8][tx] = W[(y0 + ty + r * 8) * D + x0 + tx];
    __syncthreads();
    #pragma unroll
    for (int r = 0; r < 4; r++) {
        int n = x0 + ty + r * 8;
        int k = y0 + tx;
        float v = t[tx][ty + r * 8];
        __nv_bfloat16 h = __float2bfloat16(v);
        __nv_bfloat16 l = __float2bfloat16(v - __bfloat162float(h));
        g_Bh[n * D + k] = h;
        g_Bl[n * D + k] = l;
    }
}

// ---------------------------------------------------------------------------
// 2-product split-W GEMM via mma.sync: Uh = bf16( Ah @ (Wh + Wl) )
// grid (D/BN=4, NDRUGS/BM=32), 256 threads, double-buffered cp.async
// ---------------------------------------------------------------------------
__global__ __launch_bounds__(256, 1) void dedicom_mma_kernel()
{
    extern __shared__ char smem[];
    const int tid  = threadIdx.x;
    const int wid  = tid >> 5;
    const int lane = tid & 31;
    const int m0 = blockIdx.y * BM;
    const int n0 = blockIdx.x * BN;
    const uint32_t sbase = smem_to_u32(smem);

    const int wm = (wid & 3) * 32;
    const int wn = (wid >> 2) * 64;

    float acc[2][8][4];
    #pragma unroll
    for (int a = 0; a < 2; a++)
        #pragma unroll
        for (int b = 0; b < 8; b++)
            #pragma unroll
            for (int c = 0; c < 4; c++) acc[a][b][c] = 0.f;

    auto load_stage = [&](int kc, int stg) {
        const int k0 = kc * BK;
        const uint32_t b = sbase + stg * STAGE_BYTES;
        #pragma unroll
        for (int t = tid; t < 1024; t += 256) {
            int m = t >> 3, j = t & 7;
            uint32_t sw = SMEM_SWIZZLE_128B((uint32_t)(m * 128 + j * 16));
            CP_ASYNC16(b + AH_OFF + sw, (const char*)(g_Ah + (m0 + m) * D + k0) + j * 16);
            CP_ASYNC16(b + BH_OFF + sw, (const char*)(g_Bh + (n0 + m) * D + k0) + j * 16);
            CP_ASYNC16(b + BL_OFF + sw, (const char*)(g_Bl + (n0 + m) * D + k0) + j * 16);
        }
    };

    load_stage(0, 0); CP_COMMIT();

    const int NKC = D / BK;   // 8
    for (int kc = 0; kc < NKC; kc++) {
        if (kc + 1 < NKC) { load_stage(kc + 1, (kc + 1) & 1); CP_COMMIT(); CP_WAIT(1); }
        else              { CP_WAIT(0); }
        __syncthreads();

        const uint32_t sb = sbase + (kc & 1) * STAGE_BYTES;

        #pragma unroll
        for (int ks = 0; ks < BK / 16; ks++) {
            uint32_t ah[2][4], bh[4][4], bl[4][4];

            #pragma unroll
            for (int mt = 0; mt < 2; mt++) {
                uint32_t off = SMEM_SWIZZLE_128B(
                    (uint32_t)((wm + mt * 16 + (lane & 15)) * 128 + ks * 32 + (lane >> 4) * 16));
                ldsm_x4(ah[mt][0], ah[mt][1], ah[mt][2], ah[mt][3], sb + AH_OFF + off);
            }
            #pragma unroll
            for (int p = 0; p < 4; p++) {
                uint32_t off = SMEM_SWIZZLE_128B(
                    (uint32_t)((wn + p * 16 + ((lane >> 4) * 8) + (lane & 7)) * 128
                               + ks * 32 + ((lane >> 3) & 1) * 16));
                ldsm_x4(bh[p][0], bh[p][1], bh[p][2], bh[p][3], sb + BH_OFF + off);
                ldsm_x4(bl[p][0], bl[p][1], bl[p][2], bl[p][3], sb + BL_OFF + off);
            }
            #pragma unroll
            for (int mt = 0; mt < 2; mt++) {
                #pragma unroll
                for (int p = 0; p < 4; p++) {
                    mma_bf16(acc[mt][2 * p + 0], ah[mt], bh[p][0], bh[p][1]);
                    mma_bf16(acc[mt][2 * p + 0], ah[mt], bl[p][0], bl[p][1]);
                    mma_bf16(acc[mt][2 * p + 1], ah[mt], bh[p][2], bh[p][3]);
                    mma_bf16(acc[mt][2 * p + 1], ah[mt], bl[p][2], bl[p][3]);
                }
            }
        }
        __syncthreads();
    }

    // epilogue: write Uh as bf16 pairs (no diag scale — folded into edge col side)
    const int g  = lane >> 2;
    const int c2 = (lane & 3) * 2;
    #pragma unroll
    for (int mt = 0; mt < 2; mt++) {
        const int row0 = m0 + wm + mt * 16 + g;
        #pragma unroll
        for (int nt = 0; nt < 8; nt++) {
            const int col = wn + nt * 8 + c2;
            __nv_bfloat162 v0 = __floats2bfloat162_rn(acc[mt][nt][0], acc[mt][nt][1]);
            __nv_bfloat162 v1 = __floats2bfloat162_rn(acc[mt][nt][2], acc[mt][nt][3]);
            *(__nv_bfloat162*)(g_Uh + (long)row0 * D + n0 + col)       = v0;
            *(__nv_bfloat162*)(g_Uh + (long)(row0 + 8) * D + n0 + col) = v1;
        }
    }
}

// ---------------------------------------------------------------------------
// Phase 2: one warp per edge — score = Uh[r] . Ah[c].
// Mainloop is pure HFMA2.BF16_V2 (no conversions); each bf16x2 accumulator
// slot sums only 2 products before fp32 up-conversion, keeping rounding tiny.
// ---------------------------------------------------------------------------
__global__ __launch_bounds__(256) void dedicom_edge_kernel(
    const int* __restrict__ edges,
    float* __restrict__ out,
    int n_edges)
{
    const int w    = (blockIdx.x * blockDim.x + threadIdx.x) >> 5;
    const int lane = threadIdx.x & 31;
    if (w >= n_edges) return;

    const int r = edges[w];
    const int c = edges[n_edges + w];

    const uint4* vr = (const uint4*)(g_Uh + (long)r * D);   // 64 uint4 per row
    const uint4* zc = (const uint4*)(g_Ah + (long)c * D);

    __nv_bfloat162 z2 = __floats2bfloat162_rn(0.f, 0.f);
    __nv_bfloat162 q0 = z2, q1 = z2, q2 = z2, q3 = z2;

    #pragma unroll
    for (int i = 0; i < 2; i++) {
        uint4 a = __ldg(&vr[lane + i * 32]);
        uint4 b = __ldg(&zc[lane + i * 32]);
        q0 = __hfma2(*(const __nv_bfloat162*)&a.x, *(const __nv_bfloat162*)&b.x, q0);
        q1 = __hfma2(*(const __nv_bfloat162*)&a.y, *(const __nv_bfloat162*)&b.y, q1);
        q2 = __hfma2(*(const __nv_bfloat162*)&a.z, *(const __nv_bfloat162*)&b.z, q2);
        q3 = __hfma2(*(const __nv_bfloat162*)&a.w, *(const __nv_bfloat162*)&b.w, q3);
    }

    // fp32 final reduction (bf16 tree-adds here would cost ~2e-3 rel err)
    float2 f0 = __bfloat1622float2(q0);
    float2 f1 = __bfloat1622float2(q1);
    float2 f2 = __bfloat1622float2(q2);
    float2 f3 = __bfloat1622float2(q3);
    float acc = ((f0.x + f0.y) + (f1.x + f1.y)) + ((f2.x + f2.y) + (f3.x + f3.y));

    #pragma unroll
    for (int o = 16; o; o >>= 1) acc += __shfl_xor_sync(0xffffffffu, acc, o);

    if (lane == 0) out[w] = 1.f / (1.f + __expf(-acc));
}

// ---------------------------------------------------------------------------
// Launch
// ---------------------------------------------------------------------------
extern "C" void kernel_launch(void* const* d_in, const int* in_sizes, int n_in,
                              void* d_out, int out_size)
{
    const float* z     = (const float*)d_in[0];   // [4096, 512]
    const float* W     = (const float*)d_in[1];   // [512, 512]
    const float* ldiag = (const float*)d_in[2];   // [10, 512]
    const int*   edges = (const int*)d_in[3];     // [2, n_edges] int32
    const int*   idxp  = (const int*)d_in[4];     // scalar

    const int n_drugs = in_sizes[0] / D;
    const int n_edges = in_sizes[3] / 2;

    static int smem_set = 0;
    if (!smem_set) {
        cudaFuncSetAttribute(dedicom_mma_kernel,
                             cudaFuncAttributeMaxDynamicSharedMemorySize, SM_GEMM);
        smem_set = 1;
    }

    prep_a_kernel<<<(n_drugs * D / 4 + 255) / 256, 256>>>(z, ldiag, idxp);
    prep_w_kernel<<<dim3(D / 32, D / 32), dim3(32, 8)>>>(W);

    dim3 gm(D / BN, n_drugs / BM);
    dedicom_mma_kernel<<<gm, 256, SM_GEMM>>>();

    int blocks = (n_edges + 7) / 8;
    dedicom_edge_kernel<<<blocks, 256>>>(edges, (float*)d_out, n_edges);
}